// round 1
// baseline (speedup 1.0000x reference)
#include <cuda_runtime.h>
#include <cuda_bf16.h>
#include <cstdint>

#define N_NODES 50000
#define N_EDGES 800000
#define HDIM    256
#define N_LAYERS 3

// ---------------- scratch (no allocation allowed) ----------------
__device__ float g_xcur[N_NODES * HDIM];
__device__ float g_acc [N_NODES * HDIM];
__device__ float g_t0  [N_NODES * HDIM];
__device__ float g_t1  [N_NODES * HDIM];
__device__ int   g_src [N_EDGES];
__device__ int   g_dst [N_EDGES];
__device__ int   g_is64;

// ---------------- int64 vs int32 edge_index detection ----------------
__global__ void detect_kernel(const unsigned* __restrict__ ei) {
    if (threadIdx.x == 0 && blockIdx.x == 0) {
        int all0 = 1;
        #pragma unroll 1
        for (int i = 1; i < 128; i += 2) {
            if (ei[i] != 0u) { all0 = 0; break; }
        }
        g_is64 = all0;
    }
}

__global__ void convert_idx_kernel(const void* __restrict__ ei) {
    int i = blockIdx.x * blockDim.x + threadIdx.x;
    if (i >= N_EDGES) return;
    if (g_is64) {
        const long long* p = (const long long*)ei;
        g_src[i] = (int)p[i];
        g_dst[i] = (int)p[N_EDGES + i];
    } else {
        const int* p = (const int*)ei;
        g_src[i] = p[i];
        g_dst[i] = p[N_EDGES + i];
    }
}

// ---------------- copy ----------------
__global__ void copy_kernel(const float4* __restrict__ src, float4* __restrict__ dst, int n4) {
    int i = blockIdx.x * blockDim.x + threadIdx.x;
    if (i < n4) dst[i] = src[i];
}

// ---------------- edge phase ----------------
__device__ __forceinline__ void red_add_v4(float* p, float4 v) {
    asm volatile("red.global.add.v4.f32 [%0], {%1,%2,%3,%4};"
                 :: "l"(p), "f"(v.x), "f"(v.y), "f"(v.z), "f"(v.w) : "memory");
}

// acc must be pre-initialized to x; after this kernel acc = x + segment_sum(relu(x[src]+e), dst)
__global__ __launch_bounds__(256) void edge_kernel(
    const float* __restrict__ x,
    float* __restrict__ acc,
    const float* __restrict__ edge_attr,   // [E,3]
    const float* __restrict__ We,          // [3,256]
    const float* __restrict__ be)          // [256]
{
    __shared__ float sW[3 * HDIM];
    __shared__ float sB[HDIM];
    int tid = threadIdx.x;
    for (int i = tid; i < 3 * HDIM; i += 256) sW[i] = We[i];
    if (tid < HDIM) sB[tid] = be[tid];
    __syncthreads();

    int warp = tid >> 5;
    int lane = tid & 31;
    int nwarps = gridDim.x * 8;

    for (int e = blockIdx.x * 8 + warp; e < N_EDGES; e += nwarps) {
        int s = g_src[e];
        int d = g_dst[e];
        float a0 = __ldg(&edge_attr[e * 3 + 0]);
        float a1 = __ldg(&edge_attr[e * 3 + 1]);
        float a2 = __ldg(&edge_attr[e * 3 + 2]);
        const float4* xs = (const float4*)(x + (size_t)s * HDIM);
        float* ad = acc + (size_t)d * HDIM;
        #pragma unroll
        for (int j = 0; j < 2; j++) {
            int h = lane * 8 + j * 4;
            float4 xv = __ldg(&xs[h >> 2]);
            float4 m;
            m.x = fmaxf(xv.x + fmaf(a0, sW[h+0], fmaf(a1, sW[HDIM+h+0], fmaf(a2, sW[2*HDIM+h+0], sB[h+0]))), 0.f);
            m.y = fmaxf(xv.y + fmaf(a0, sW[h+1], fmaf(a1, sW[HDIM+h+1], fmaf(a2, sW[2*HDIM+h+1], sB[h+1]))), 0.f);
            m.z = fmaxf(xv.z + fmaf(a0, sW[h+2], fmaf(a1, sW[HDIM+h+2], fmaf(a2, sW[2*HDIM+h+2], sB[h+2]))), 0.f);
            m.w = fmaxf(xv.w + fmaf(a0, sW[h+3], fmaf(a1, sW[HDIM+h+3], fmaf(a2, sW[2*HDIM+h+3], sB[h+3]))), 0.f);
            red_add_v4(ad + h, m);
        }
    }
}

// ---------------- fp32 SGEMM with fused epilogue ----------------
// C[m][n] = epilogue( sum_k A[m][k]*W[k][n] + bias[n] )
// mode 0: none   mode 1: relu   mode 2: relu + res[m][n]
#define BM 128
#define BN 128
#define BK 8

__global__ __launch_bounds__(256) void sgemm_epi(
    const float* __restrict__ A,      // [M,256]
    const float* __restrict__ W,      // [256,BN*gridDim.y] row-major K x N
    const float* __restrict__ bias,   // [256]
    float* __restrict__ C,            // [M,256]
    const float* __restrict__ res,    // [M,256] or null
    int M, int mode)
{
    __shared__ float As[BK][BM + 4];
    __shared__ float Bs[BK][BN + 4];

    int bm = blockIdx.x * BM;
    int bn = blockIdx.y * BN;
    int tid = threadIdx.x;
    int tx = tid & 15;
    int ty = tid >> 4;

    // A-load mapping: one float4 per thread
    int arow  = tid >> 1;          // 0..127
    int acol4 = (tid & 1) * 4;     // 0 or 4
    // B-load mapping
    int brow  = tid >> 5;          // 0..7
    int bcol4 = (tid & 31) * 4;    // 0..124

    float acc[8][8];
    #pragma unroll
    for (int i = 0; i < 8; i++)
        #pragma unroll
        for (int j = 0; j < 8; j++) acc[i][j] = 0.f;

    for (int k0 = 0; k0 < HDIM; k0 += BK) {
        float4 av = make_float4(0.f, 0.f, 0.f, 0.f);
        if (bm + arow < M)
            av = *(const float4*)(A + (size_t)(bm + arow) * HDIM + k0 + acol4);
        As[acol4 + 0][arow] = av.x;
        As[acol4 + 1][arow] = av.y;
        As[acol4 + 2][arow] = av.z;
        As[acol4 + 3][arow] = av.w;

        float4 bv = *(const float4*)(W + (size_t)(k0 + brow) * HDIM + bn + bcol4);
        *(float4*)&Bs[brow][bcol4] = bv;
        __syncthreads();

        #pragma unroll
        for (int kk = 0; kk < BK; kk++) {
            float4 a0 = *(float4*)&As[kk][ty * 8];
            float4 a1 = *(float4*)&As[kk][ty * 8 + 4];
            float4 b0 = *(float4*)&Bs[kk][tx * 8];
            float4 b1 = *(float4*)&Bs[kk][tx * 8 + 4];
            float ra[8] = {a0.x, a0.y, a0.z, a0.w, a1.x, a1.y, a1.z, a1.w};
            float rb[8] = {b0.x, b0.y, b0.z, b0.w, b1.x, b1.y, b1.z, b1.w};
            #pragma unroll
            for (int i = 0; i < 8; i++)
                #pragma unroll
                for (int j = 0; j < 8; j++)
                    acc[i][j] = fmaf(ra[i], rb[j], acc[i][j]);
        }
        __syncthreads();
    }

    float bb[8];
    #pragma unroll
    for (int j = 0; j < 8; j++) bb[j] = bias[bn + tx * 8 + j];

    #pragma unroll
    for (int i = 0; i < 8; i++) {
        int row = bm + ty * 8 + i;
        if (row >= M) continue;
        size_t off = (size_t)row * HDIM + bn + tx * 8;
        float v[8];
        #pragma unroll
        for (int j = 0; j < 8; j++) {
            float t = acc[i][j] + bb[j];
            if (mode >= 1) t = fmaxf(t, 0.f);
            v[j] = t;
        }
        if (mode == 2) {
            const float* rr = res + off;
            #pragma unroll
            for (int j = 0; j < 8; j++) v[j] += rr[j];
        }
        *(float4*)(C + off)     = make_float4(v[0], v[1], v[2], v[3]);
        *(float4*)(C + off + 4) = make_float4(v[4], v[5], v[6], v[7]);
    }
}

// ---------------- launch ----------------
extern "C" void kernel_launch(void* const* d_in, const int* in_sizes, int n_in,
                              void* d_out, int out_size)
{
    const float* x         = (const float*)d_in[0];
    const void*  edge_idx  = d_in[1];
    const float* edge_attr = (const float*)d_in[2];
    const float* We        = (const float*)d_in[3];   // [3,3,256]
    const float* be        = (const float*)d_in[4];   // [3,256]
    const float* Wm        = (const float*)d_in[5];   // [3,3,256,256]
    const float* bm        = (const float*)d_in[6];   // [3,3,256]
    const float* pW1       = (const float*)d_in[7];
    const float* pb1       = (const float*)d_in[8];
    const float* pW2       = (const float*)d_in[9];
    const float* pb2       = (const float*)d_in[10];
    float* out             = (float*)d_out;

    float *xcur, *acc, *t0, *t1;
    cudaGetSymbolAddress((void**)&xcur, g_xcur);
    cudaGetSymbolAddress((void**)&acc,  g_acc);
    cudaGetSymbolAddress((void**)&t0,   g_t0);
    cudaGetSymbolAddress((void**)&t1,   g_t1);

    const int M = N_NODES;
    const int n4 = N_NODES * HDIM / 4;
    dim3 gemm_grid((M + BM - 1) / BM, HDIM / BN);

    detect_kernel<<<1, 32>>>((const unsigned*)edge_idx);
    convert_idx_kernel<<<(N_EDGES + 255) / 256, 256>>>(edge_idx);
    copy_kernel<<<(n4 + 255) / 256, 256>>>((const float4*)x, (float4*)xcur, n4);

    for (int l = 0; l < N_LAYERS; l++) {
        const float* Wel = We + (size_t)l * 3 * HDIM;
        const float* bel = be + (size_t)l * HDIM;
        const float* Wml = Wm + (size_t)l * 3 * HDIM * HDIM;
        const float* bml = bm + (size_t)l * 3 * HDIM;

        // acc = x  (so edge scatter produces x + agg)
        copy_kernel<<<(n4 + 255) / 256, 256>>>((const float4*)xcur, (float4*)acc, n4);
        edge_kernel<<<4096, 256>>>(xcur, acc, edge_attr, Wel, bel);

        // inner MLP: relu, relu, then relu(h)+x0 fused (in-place into xcur)
        sgemm_epi<<<gemm_grid, 256>>>(acc, Wml,                 bml,            t0,   nullptr, M, 1);
        sgemm_epi<<<gemm_grid, 256>>>(t0,  Wml + 1 * HDIM*HDIM, bml + 1 * HDIM, t1,   nullptr, M, 1);
        sgemm_epi<<<gemm_grid, 256>>>(t1,  Wml + 2 * HDIM*HDIM, bml + 2 * HDIM, xcur, xcur,    M, 2);
    }

    // projection head
    sgemm_epi<<<gemm_grid, 256>>>(xcur, pW1, pb1, t0,  nullptr, M, 1);
    sgemm_epi<<<gemm_grid, 256>>>(t0,   pW2, pb2, out, nullptr, M, 0);
}

// round 3
// speedup vs baseline: 1.1363x; 1.1363x over previous
#include <cuda_runtime.h>
#include <cuda_bf16.h>
#include <cstdint>

#define N_NODES 50000
#define N_EDGES 800000
#define HDIM    256
#define N_LAYERS 3

// ---------------- scratch (no allocation allowed) ----------------
__device__ float g_xcur[N_NODES * HDIM];
__device__ float g_acc [N_NODES * HDIM];
__device__ float g_t0  [N_NODES * HDIM];
__device__ float g_t1  [N_NODES * HDIM];
__device__ int   g_src [N_EDGES];
__device__ int   g_dst [N_EDGES];
__device__ int   g_is64;

// ---------------- misc kernels ----------------
__global__ void detect_kernel(const unsigned* __restrict__ ei) {
    if (threadIdx.x == 0 && blockIdx.x == 0) {
        int all0 = 1;
        #pragma unroll 1
        for (int i = 1; i < 128; i += 2) if (ei[i] != 0u) { all0 = 0; break; }
        g_is64 = all0;
    }
}
__global__ void convert_idx_kernel(const void* __restrict__ ei) {
    int i = blockIdx.x * blockDim.x + threadIdx.x;
    if (i >= N_EDGES) return;
    if (g_is64) {
        const long long* p = (const long long*)ei;
        g_src[i] = (int)p[i];
        g_dst[i] = (int)p[N_EDGES + i];
    } else {
        const int* p = (const int*)ei;
        g_src[i] = p[i];
        g_dst[i] = p[N_EDGES + i];
    }
}
__global__ void copy_kernel(const float4* __restrict__ src, float4* __restrict__ dst, int n4) {
    int i = blockIdx.x * blockDim.x + threadIdx.x;
    if (i < n4) dst[i] = src[i];
}

// ---------------- edge phase ----------------
__device__ __forceinline__ void red_add_v4(float* p, float4 v) {
    asm volatile("red.global.add.v4.f32 [%0], {%1,%2,%3,%4};"
                 :: "l"(p), "f"(v.x), "f"(v.y), "f"(v.z), "f"(v.w) : "memory");
}
__global__ __launch_bounds__(256) void edge_kernel(
    const float* __restrict__ x, float* __restrict__ acc,
    const float* __restrict__ edge_attr, const float* __restrict__ We, const float* __restrict__ be)
{
    __shared__ float sW[3 * HDIM];
    __shared__ float sB[HDIM];
    int tid = threadIdx.x;
    for (int i = tid; i < 3 * HDIM; i += 256) sW[i] = We[i];
    if (tid < HDIM) sB[tid] = be[tid];
    __syncthreads();
    int warp = tid >> 5, lane = tid & 31;
    int nwarps = gridDim.x * 8;
    for (int e = blockIdx.x * 8 + warp; e < N_EDGES; e += nwarps) {
        int s = g_src[e], d = g_dst[e];
        float a0 = __ldg(&edge_attr[e * 3 + 0]);
        float a1 = __ldg(&edge_attr[e * 3 + 1]);
        float a2 = __ldg(&edge_attr[e * 3 + 2]);
        const float4* xs = (const float4*)(x + (size_t)s * HDIM);
        float* ad = acc + (size_t)d * HDIM;
        #pragma unroll
        for (int j = 0; j < 2; j++) {
            int h = lane * 8 + j * 4;
            float4 xv = __ldg(&xs[h >> 2]);
            float4 m;
            m.x = fmaxf(xv.x + fmaf(a0, sW[h+0], fmaf(a1, sW[HDIM+h+0], fmaf(a2, sW[2*HDIM+h+0], sB[h+0]))), 0.f);
            m.y = fmaxf(xv.y + fmaf(a0, sW[h+1], fmaf(a1, sW[HDIM+h+1], fmaf(a2, sW[2*HDIM+h+1], sB[h+1]))), 0.f);
            m.z = fmaxf(xv.z + fmaf(a0, sW[h+2], fmaf(a1, sW[HDIM+h+2], fmaf(a2, sW[2*HDIM+h+2], sB[h+2]))), 0.f);
            m.w = fmaxf(xv.w + fmaf(a0, sW[h+3], fmaf(a1, sW[HDIM+h+3], fmaf(a2, sW[2*HDIM+h+3], sB[h+3]))), 0.f);
            red_add_v4(ad + h, m);
        }
    }
}

// ---------------- tf32 mma.sync GEMM, 3xTF32 split, fused epilogue ----------------
// C[m][n] = epi( sum_k A[m][k] * W[k][n] + bias[n] )
// W is plain row-major [K=256, N=256] (the dataset layout). mode 0 none, 1 relu, 2 relu+res.
#define BM 128
#define BN 128
#define KC 32
#define NCH (HDIM / KC)      // 8
// smem (floats): As[2][128][36], Bs[2][32][132]
#define AS_STRIDE 36
#define BS_STRIDE 132
#define AS_BUF (BM * AS_STRIDE)          // 4608
#define BS_BASE (2 * AS_BUF)             // 9216
#define BS_BUF (KC * BS_STRIDE)          // 4224
#define GEMM_SMEM ((2 * AS_BUF + 2 * BS_BUF) * 4)   // 70656 bytes

__device__ __forceinline__ uint32_t smem_u32(const void* p) {
    uint32_t a;
    asm("{ .reg .u64 t; cvta.to.shared.u64 t, %1; cvt.u32.u64 %0, t; }" : "=r"(a) : "l"(p));
    return a;
}
__device__ __forceinline__ void cpa16(uint32_t dst, const void* src, int nbytes) {
    asm volatile("cp.async.cg.shared.global [%0], [%1], 16, %2;" :: "r"(dst), "l"(src), "r"(nbytes) : "memory");
}
__device__ __forceinline__ uint32_t f2tf(float x) {
    uint32_t r;
    asm("cvt.rna.tf32.f32 %0, %1;" : "=r"(r) : "f"(x));
    return r;
}
__device__ __forceinline__ void mma8(float* c, uint32_t a0, uint32_t a1, uint32_t a2, uint32_t a3,
                                     uint32_t b0, uint32_t b1) {
    asm volatile("mma.sync.aligned.m16n8k8.row.col.f32.tf32.tf32.f32 "
                 "{%0,%1,%2,%3},{%4,%5,%6,%7},{%8,%9},{%0,%1,%2,%3};"
                 : "+f"(c[0]), "+f"(c[1]), "+f"(c[2]), "+f"(c[3])
                 : "r"(a0), "r"(a1), "r"(a2), "r"(a3), "r"(b0), "r"(b1));
}

__global__ __launch_bounds__(256, 1) void gemm_mma(
    const float* __restrict__ A, const float* __restrict__ W,
    const float* __restrict__ bias, float* __restrict__ C, const float* __restrict__ res,
    int M, int mode)
{
    extern __shared__ float sf[];
    const uint32_t sb = smem_u32(sf);
    const int tid  = threadIdx.x;
    const int lane = tid & 31;
    const int warp = tid >> 5;
    const int g = lane >> 2, t = lane & 3;
    const int wm = warp & 3;        // 4 warps along M
    const int wn = warp >> 2;       // 2 warps along N
    const int bm = blockIdx.x * BM;
    const int bn = blockIdx.y * BN;

    float acc[2][8][4];
    #pragma unroll
    for (int i = 0; i < 2; i++)
        #pragma unroll
        for (int j = 0; j < 8; j++)
            #pragma unroll
            for (int q = 0; q < 4; q++) acc[i][j][q] = 0.f;

    // ---- async stage loader ----
    auto issue = [&](int ch, int buf) {
        const int k0 = ch * KC;
        #pragma unroll
        for (int i = 0; i < 4; i++) {
            int idx = tid + i * 256;
            int row = idx >> 3, c = idx & 7;
            uint32_t dst = sb + (buf * AS_BUF + row * AS_STRIDE + c * 4) * 4;
            const float* src = A + (size_t)(bm + row) * HDIM + k0 + c * 4;
            cpa16(dst, src, (bm + row < M) ? 16 : 0);
        }
        #pragma unroll
        for (int i = 0; i < 4; i++) {
            int idx = tid + i * 256;
            int row = idx >> 5, c = idx & 31;
            uint32_t dst = sb + (BS_BASE + buf * BS_BUF + row * BS_STRIDE + c * 4) * 4;
            const float* src = W + (size_t)(k0 + row) * HDIM + bn + c * 4;
            cpa16(dst, src, 16);
        }
        asm volatile("cp.async.commit_group;" ::: "memory");
    };

    issue(0, 0);
    issue(1, 1);

    for (int ch = 0; ch < NCH; ch++) {
        const int buf = ch & 1;
        if (ch == NCH - 1) asm volatile("cp.async.wait_group 0;" ::: "memory");
        else               asm volatile("cp.async.wait_group 1;" ::: "memory");
        __syncthreads();

        const float* as = sf + buf * AS_BUF;
        const float* bs = sf + BS_BASE + buf * BS_BUF;

        #pragma unroll
        for (int kk = 0; kk < KC / 8; kk++) {
            // A fragments (hi + lo) for both 16-row tiles
            uint32_t ah[2][4], al[2][4];
            #pragma unroll
            for (int mi = 0; mi < 2; mi++) {
                int mrow = wm * 32 + mi * 16;
                float r0 = as[(mrow + g)     * AS_STRIDE + kk * 8 + t];
                float r1 = as[(mrow + g + 8) * AS_STRIDE + kk * 8 + t];
                float r2 = as[(mrow + g)     * AS_STRIDE + kk * 8 + t + 4];
                float r3 = as[(mrow + g + 8) * AS_STRIDE + kk * 8 + t + 4];
                ah[mi][0] = f2tf(r0); ah[mi][1] = f2tf(r1);
                ah[mi][2] = f2tf(r2); ah[mi][3] = f2tf(r3);
                al[mi][0] = __float_as_uint(r0 - __uint_as_float(ah[mi][0]));
                al[mi][1] = __float_as_uint(r1 - __uint_as_float(ah[mi][1]));
                al[mi][2] = __float_as_uint(r2 - __uint_as_float(ah[mi][2]));
                al[mi][3] = __float_as_uint(r3 - __uint_as_float(ah[mi][3]));
            }
            #pragma unroll
            for (int half = 0; half < 2; half++) {
                uint32_t bh[4][2], bl[4][2];
                #pragma unroll
                for (int ni = 0; ni < 4; ni++) {
                    int n = wn * 64 + half * 32 + ni * 8 + g;
                    float q0 = bs[(kk * 8 + t)     * BS_STRIDE + n];
                    float q1 = bs[(kk * 8 + t + 4) * BS_STRIDE + n];
                    bh[ni][0] = f2tf(q0); bh[ni][1] = f2tf(q1);
                    bl[ni][0] = __float_as_uint(q0 - __uint_as_float(bh[ni][0]));
                    bl[ni][1] = __float_as_uint(q1 - __uint_as_float(bh[ni][1]));
                }
                #pragma unroll
                for (int mi = 0; mi < 2; mi++)
                    #pragma unroll
                    for (int ni = 0; ni < 4; ni++) {
                        float* c = acc[mi][half * 4 + ni];
                        mma8(c, ah[mi][0], ah[mi][1], ah[mi][2], ah[mi][3], bh[ni][0], bh[ni][1]);
                        mma8(c, ah[mi][0], ah[mi][1], ah[mi][2], ah[mi][3], bl[ni][0], bl[ni][1]);
                        mma8(c, al[mi][0], al[mi][1], al[mi][2], al[mi][3], bh[ni][0], bh[ni][1]);
                    }
            }
        }
        __syncthreads();
        if (ch + 2 < NCH) issue(ch + 2, buf);
    }

    // ---- epilogue: bias / relu / residual, direct float2 stores ----
    #pragma unroll
    for (int ni = 0; ni < 8; ni++) {
        int col = bn + wn * 64 + ni * 8 + t * 2;
        float2 bb = *(const float2*)(bias + col);
        #pragma unroll
        for (int mi = 0; mi < 2; mi++) {
            float* c = acc[mi][ni];
            int row0 = bm + wm * 32 + mi * 16 + g;
            int row1 = row0 + 8;
            if (row0 < M) {
                size_t off = (size_t)row0 * HDIM + col;
                float vx = c[0] + bb.x, vy = c[1] + bb.y;
                if (mode >= 1) { vx = fmaxf(vx, 0.f); vy = fmaxf(vy, 0.f); }
                if (mode == 2) { float2 rr = *(const float2*)(res + off); vx += rr.x; vy += rr.y; }
                *(float2*)(C + off) = make_float2(vx, vy);
            }
            if (row1 < M) {
                size_t off = (size_t)row1 * HDIM + col;
                float vx = c[2] + bb.x, vy = c[3] + bb.y;
                if (mode >= 1) { vx = fmaxf(vx, 0.f); vy = fmaxf(vy, 0.f); }
                if (mode == 2) { float2 rr = *(const float2*)(res + off); vx += rr.x; vy += rr.y; }
                *(float2*)(C + off) = make_float2(vx, vy);
            }
        }
    }
}

// ---------------- launch ----------------
extern "C" void kernel_launch(void* const* d_in, const int* in_sizes, int n_in,
                              void* d_out, int out_size)
{
    const float* x         = (const float*)d_in[0];
    const void*  edge_idx  = d_in[1];
    const float* edge_attr = (const float*)d_in[2];
    const float* We        = (const float*)d_in[3];
    const float* be        = (const float*)d_in[4];
    const float* Wm        = (const float*)d_in[5];
    const float* bmv       = (const float*)d_in[6];
    const float* pW1       = (const float*)d_in[7];
    const float* pb1       = (const float*)d_in[8];
    const float* pW2       = (const float*)d_in[9];
    const float* pb2       = (const float*)d_in[10];
    float* out             = (float*)d_out;

    float *xcur, *acc, *t0, *t1;
    cudaGetSymbolAddress((void**)&xcur, g_xcur);
    cudaGetSymbolAddress((void**)&acc,  g_acc);
    cudaGetSymbolAddress((void**)&t0,   g_t0);
    cudaGetSymbolAddress((void**)&t1,   g_t1);

    static int smem_set = 0;
    if (!smem_set) {
        cudaFuncSetAttribute(gemm_mma, cudaFuncAttributeMaxDynamicSharedMemorySize, GEMM_SMEM);
        smem_set = 1;
    }

    const int M = N_NODES;
    const int n4 = N_NODES * HDIM / 4;
    dim3 ggrid((M + BM - 1) / BM, HDIM / BN);   // 391 x 2
    const size_t WSZ = (size_t)HDIM * HDIM;

    detect_kernel<<<1, 32>>>((const unsigned*)edge_idx);
    convert_idx_kernel<<<(N_EDGES + 255) / 256, 256>>>(edge_idx);
    copy_kernel<<<(n4 + 255) / 256, 256>>>((const float4*)x, (float4*)xcur, n4);

    for (int l = 0; l < N_LAYERS; l++) {
        const float* Wel = We + (size_t)l * 3 * HDIM;
        const float* bel = be + (size_t)l * HDIM;
        const float* Wml = Wm + (size_t)l * 3 * WSZ;
        const float* bml = bmv + (size_t)l * 3 * HDIM;

        copy_kernel<<<(n4 + 255) / 256, 256>>>((const float4*)xcur, (float4*)acc, n4);
        edge_kernel<<<4096, 256>>>(xcur, acc, edge_attr, Wel, bel);

        gemm_mma<<<ggrid, 256, GEMM_SMEM>>>(acc, Wml,           bml,            t0,   nullptr, M, 1);
        gemm_mma<<<ggrid, 256, GEMM_SMEM>>>(t0,  Wml + WSZ,     bml + HDIM,     t1,   nullptr, M, 1);
        gemm_mma<<<ggrid, 256, GEMM_SMEM>>>(t1,  Wml + 2 * WSZ, bml + 2 * HDIM, xcur, xcur,    M, 2);
    }
    gemm_mma<<<ggrid, 256, GEMM_SMEM>>>(xcur, pW1, pb1, t0,  nullptr, M, 1);
    gemm_mma<<<ggrid, 256, GEMM_SMEM>>>(t0,   pW2, pb2, out, nullptr, M, 0);
}

// round 4
// speedup vs baseline: 1.3215x; 1.1629x over previous
#include <cuda_runtime.h>
#include <cuda_bf16.h>
#include <cstdint>

#define N_NODES 50000
#define N_EDGES 800000
#define HDIM    256
#define N_LAYERS 3
#define NWEIGHTS 11

// ---------------- scratch (no allocation allowed) ----------------
__device__ float g_xcur[N_NODES * HDIM];
__device__ float g_acc [N_NODES * HDIM];
__device__ float g_t0  [N_NODES * HDIM];
__device__ float g_t1  [N_NODES * HDIM];
// packed pre-split weights: [w][ch(8)][n(256)][unit(16)][4 floats]  (swizzled)
__device__ float g_wpk[NWEIGHTS * 8 * 256 * 64];
__device__ int   g_src [N_EDGES];
__device__ int   g_dst [N_EDGES];
__device__ int   g_is64;

// ---------------- helpers ----------------
__device__ __forceinline__ uint32_t smem_u32(const void* p) {
    uint32_t a;
    asm("{ .reg .u64 t; cvta.to.shared.u64 t, %1; cvt.u32.u64 %0, t; }" : "=r"(a) : "l"(p));
    return a;
}
__device__ __forceinline__ void cpa16(uint32_t dst, const void* src, int nbytes) {
    asm volatile("cp.async.cg.shared.global [%0], [%1], 16, %2;" :: "r"(dst), "l"(src), "r"(nbytes) : "memory");
}
__device__ __forceinline__ uint32_t f2tf(float x) {
    uint32_t r;
    asm("cvt.rna.tf32.f32 %0, %1;" : "=r"(r) : "f"(x));
    return r;
}
__device__ __forceinline__ void mma8(float* c, uint32_t a0, uint32_t a1, uint32_t a2, uint32_t a3,
                                     uint32_t b0, uint32_t b1) {
    asm volatile("mma.sync.aligned.m16n8k8.row.col.f32.tf32.tf32.f32 "
                 "{%0,%1,%2,%3},{%4,%5,%6,%7},{%8,%9},{%0,%1,%2,%3};"
                 : "+f"(c[0]), "+f"(c[1]), "+f"(c[2]), "+f"(c[3])
                 : "r"(a0), "r"(a1), "r"(a2), "r"(a3), "r"(b0), "r"(b1));
}

// ---------------- misc kernels ----------------
__global__ void detect_kernel(const unsigned* __restrict__ ei) {
    if (threadIdx.x == 0 && blockIdx.x == 0) {
        int all0 = 1;
        #pragma unroll 1
        for (int i = 1; i < 128; i += 2) if (ei[i] != 0u) { all0 = 0; break; }
        g_is64 = all0;
    }
}
__global__ void convert_idx_kernel(const void* __restrict__ ei) {
    int i = blockIdx.x * blockDim.x + threadIdx.x;
    if (i >= N_EDGES) return;
    if (g_is64) {
        const long long* p = (const long long*)ei;
        g_src[i] = (int)p[i];
        g_dst[i] = (int)p[N_EDGES + i];
    } else {
        const int* p = (const int*)ei;
        g_src[i] = p[i];
        g_dst[i] = p[N_EDGES + i];
    }
}
__global__ void copy_kernel(const float4* __restrict__ src, float4* __restrict__ dst, int n4) {
    int i = blockIdx.x * blockDim.x + threadIdx.x;
    if (i < n4) dst[i] = src[i];
}

// pre-split + transpose + fragment-pack + swizzle all 11 weight matrices.
// source W[k][n] row-major. dest: [w][ch=k/32][n][u][4]:
//   u = ((kk*4 + t) ^ (n&7)),  kk=(k>>3)&3, t=k&3, half=(k>>2)&1
//   floats: [0..1] = hi(k=t, k=t+4)  [2..3] = lo(k=t, k=t+4)
__global__ void prep_weights(const float* __restrict__ Wm, const float* __restrict__ pW1,
                             const float* __restrict__ pW2) {
    int w = blockIdx.y;
    const float* src = (w < 9) ? (Wm + (size_t)w * HDIM * HDIM) : ((w == 9) ? pW1 : pW2);
    int k = blockIdx.x;           // 0..255
    int n = threadIdx.x;          // 0..255
    float v = src[k * HDIM + n];
    float hi = __uint_as_float(f2tf(v));
    float lo = v - hi;
    int ch = k >> 5, kk = (k >> 3) & 3, t = k & 3, half = (k >> 2) & 1;
    int u = (kk * 4 + t) ^ (n & 7);
    size_t base = ((((size_t)w * 8 + ch) * 256 + n) * 16 + u) * 4;
    g_wpk[base + half]     = hi;
    g_wpk[base + 2 + half] = lo;
}

// ---------------- edge phase ----------------
__device__ __forceinline__ void red_add_v4(float* p, float4 v) {
    asm volatile("red.global.add.v4.f32 [%0], {%1,%2,%3,%4};"
                 :: "l"(p), "f"(v.x), "f"(v.y), "f"(v.z), "f"(v.w) : "memory");
}
__global__ __launch_bounds__(256) void edge_kernel(
    const float* __restrict__ x, float* __restrict__ acc,
    const float* __restrict__ edge_attr, const float* __restrict__ We, const float* __restrict__ be)
{
    __shared__ float sW[3 * HDIM];
    __shared__ float sB[HDIM];
    int tid = threadIdx.x;
    for (int i = tid; i < 3 * HDIM; i += 256) sW[i] = We[i];
    if (tid < HDIM) sB[tid] = be[tid];
    __syncthreads();
    int warp = tid >> 5, lane = tid & 31;
    int nwarps = gridDim.x * 8;
    for (int e = blockIdx.x * 8 + warp; e < N_EDGES; e += nwarps) {
        int s = g_src[e], d = g_dst[e];
        float a0 = __ldg(&edge_attr[e * 3 + 0]);
        float a1 = __ldg(&edge_attr[e * 3 + 1]);
        float a2 = __ldg(&edge_attr[e * 3 + 2]);
        const float4* xs = (const float4*)(x + (size_t)s * HDIM);
        float* ad = acc + (size_t)d * HDIM;
        #pragma unroll
        for (int j = 0; j < 2; j++) {
            int h = lane * 8 + j * 4;
            float4 xv = __ldg(&xs[h >> 2]);
            float4 m;
            m.x = fmaxf(xv.x + fmaf(a0, sW[h+0], fmaf(a1, sW[HDIM+h+0], fmaf(a2, sW[2*HDIM+h+0], sB[h+0]))), 0.f);
            m.y = fmaxf(xv.y + fmaf(a0, sW[h+1], fmaf(a1, sW[HDIM+h+1], fmaf(a2, sW[2*HDIM+h+1], sB[h+1]))), 0.f);
            m.z = fmaxf(xv.z + fmaf(a0, sW[h+2], fmaf(a1, sW[HDIM+h+2], fmaf(a2, sW[2*HDIM+h+2], sB[h+2]))), 0.f);
            m.w = fmaxf(xv.w + fmaf(a0, sW[h+3], fmaf(a1, sW[HDIM+h+3], fmaf(a2, sW[2*HDIM+h+3], sB[h+3]))), 0.f);
            red_add_v4(ad + h, m);
        }
    }
}

// ---------------- tf32 mma GEMM v2: pre-split W, swizzled B, 2 CTAs/SM ----------------
#define BM 128
#define BN 128
#define KC 32
#define NCH (HDIM / KC)          // 8
#define AS_STRIDE 36
#define AS_BUF (BM * AS_STRIDE)  // 4608 floats
#define BS_BASE (2 * AS_BUF)     // 9216 floats
#define BS_BUF 8192              // 128 n * 64 floats
#define GEMM_SMEM ((2 * AS_BUF + 2 * BS_BUF) * 4)   // 102400 bytes

__global__ __launch_bounds__(256, 2) void gemm_mma(
    const float* __restrict__ A, const float* __restrict__ Wpk,
    const float* __restrict__ bias, float* __restrict__ C, const float* __restrict__ res,
    int M, int mode)
{
    extern __shared__ float sf[];
    const uint32_t sb = smem_u32(sf);
    const int tid  = threadIdx.x;
    const int lane = tid & 31;
    const int warp = tid >> 5;
    const int g = lane >> 2, t = lane & 3;
    const int wm = warp & 3;        // 4 warps along M
    const int wn = warp >> 2;       // 2 warps along N
    const int bm = blockIdx.x * BM;
    const int bn = blockIdx.y * BN;

    float acc[2][8][4];
    #pragma unroll
    for (int i = 0; i < 2; i++)
        #pragma unroll
        for (int j = 0; j < 8; j++)
            #pragma unroll
            for (int q = 0; q < 4; q++) acc[i][j][q] = 0.f;

    auto issue = [&](int ch, int buf) {
        // A: 128 rows x 32 floats
        #pragma unroll
        for (int i = 0; i < 4; i++) {
            int idx = tid + i * 256;
            int row = idx >> 3, c = idx & 7;
            uint32_t dst = sb + (buf * AS_BUF + row * AS_STRIDE + c * 4) * 4;
            const float* src = A + (size_t)(bm + row) * HDIM + ch * KC + c * 4;
            cpa16(dst, src, (bm + row < M) ? 16 : 0);
        }
        // B: 128 n-rows x 64 floats (pre-packed, swizzle baked) -> straight copy
        const float* wsrc = Wpk + ((size_t)ch * 256 + bn) * 64;
        #pragma unroll
        for (int i = 0; i < 8; i++) {
            int idx = tid + i * 256;          // 0..2047 (16B units)
            uint32_t dst = sb + (BS_BASE + buf * BS_BUF + idx * 4) * 4;
            cpa16(dst, wsrc + idx * 4, 16);
        }
        asm volatile("cp.async.commit_group;" ::: "memory");
    };

    issue(0, 0);
    issue(1, 1);

    for (int ch = 0; ch < NCH; ch++) {
        const int buf = ch & 1;
        if (ch == NCH - 1) asm volatile("cp.async.wait_group 0;" ::: "memory");
        else               asm volatile("cp.async.wait_group 1;" ::: "memory");
        __syncthreads();

        const float* as = sf + buf * AS_BUF;
        const float* bs = sf + BS_BASE + buf * BS_BUF;

        #pragma unroll
        for (int kk = 0; kk < KC / 8; kk++) {
            uint32_t ah[2][4], al[2][4];
            #pragma unroll
            for (int mi = 0; mi < 2; mi++) {
                int mrow = wm * 32 + mi * 16;
                float r0 = as[(mrow + g)     * AS_STRIDE + kk * 8 + t];
                float r1 = as[(mrow + g + 8) * AS_STRIDE + kk * 8 + t];
                float r2 = as[(mrow + g)     * AS_STRIDE + kk * 8 + t + 4];
                float r3 = as[(mrow + g + 8) * AS_STRIDE + kk * 8 + t + 4];
                ah[mi][0] = f2tf(r0); ah[mi][1] = f2tf(r1);
                ah[mi][2] = f2tf(r2); ah[mi][3] = f2tf(r3);
                al[mi][0] = __float_as_uint(r0 - __uint_as_float(ah[mi][0]));
                al[mi][1] = __float_as_uint(r1 - __uint_as_float(ah[mi][1]));
                al[mi][2] = __float_as_uint(r2 - __uint_as_float(ah[mi][2]));
                al[mi][3] = __float_as_uint(r3 - __uint_as_float(ah[mi][3]));
            }
            #pragma unroll
            for (int half = 0; half < 2; half++) {
                float2 bh[4], bl[4];
                #pragma unroll
                for (int ni = 0; ni < 4; ni++) {
                    int n = wn * 64 + half * 32 + ni * 8 + g;
                    int u = (kk * 4 + t) ^ g;       // n&7 == g
                    const float* p = bs + n * 64 + u * 4;
                    bh[ni] = *(const float2*)(p);
                    bl[ni] = *(const float2*)(p + 2);
                }
                #pragma unroll
                for (int mi = 0; mi < 2; mi++)
                    #pragma unroll
                    for (int ni = 0; ni < 4; ni++) {
                        float* c = acc[mi][half * 4 + ni];
                        uint32_t b0h = __float_as_uint(bh[ni].x), b1h = __float_as_uint(bh[ni].y);
                        uint32_t b0l = __float_as_uint(bl[ni].x), b1l = __float_as_uint(bl[ni].y);
                        mma8(c, ah[mi][0], ah[mi][1], ah[mi][2], ah[mi][3], b0h, b1h);
                        mma8(c, ah[mi][0], ah[mi][1], ah[mi][2], ah[mi][3], b0l, b1l);
                        mma8(c, al[mi][0], al[mi][1], al[mi][2], al[mi][3], b0h, b1h);
                    }
            }
        }
        __syncthreads();
        if (ch + 2 < NCH) issue(ch + 2, buf);
    }

    // ---- epilogue ----
    #pragma unroll
    for (int ni = 0; ni < 8; ni++) {
        int col = bn + wn * 64 + ni * 8 + t * 2;
        float2 bb = *(const float2*)(bias + col);
        #pragma unroll
        for (int mi = 0; mi < 2; mi++) {
            float* c = acc[mi][ni];
            int row0 = bm + wm * 32 + mi * 16 + g;
            int row1 = row0 + 8;
            if (row0 < M) {
                size_t off = (size_t)row0 * HDIM + col;
                float vx = c[0] + bb.x, vy = c[1] + bb.y;
                if (mode >= 1) { vx = fmaxf(vx, 0.f); vy = fmaxf(vy, 0.f); }
                if (mode == 2) { float2 rr = *(const float2*)(res + off); vx += rr.x; vy += rr.y; }
                *(float2*)(C + off) = make_float2(vx, vy);
            }
            if (row1 < M) {
                size_t off = (size_t)row1 * HDIM + col;
                float vx = c[2] + bb.x, vy = c[3] + bb.y;
                if (mode >= 1) { vx = fmaxf(vx, 0.f); vy = fmaxf(vy, 0.f); }
                if (mode == 2) { float2 rr = *(const float2*)(res + off); vx += rr.x; vy += rr.y; }
                *(float2*)(C + off) = make_float2(vx, vy);
            }
        }
    }
}

// ---------------- launch ----------------
extern "C" void kernel_launch(void* const* d_in, const int* in_sizes, int n_in,
                              void* d_out, int out_size)
{
    const float* x         = (const float*)d_in[0];
    const void*  edge_idx  = d_in[1];
    const float* edge_attr = (const float*)d_in[2];
    const float* We        = (const float*)d_in[3];
    const float* be        = (const float*)d_in[4];
    const float* Wm        = (const float*)d_in[5];
    const float* bmv       = (const float*)d_in[6];
    const float* pW1       = (const float*)d_in[7];
    const float* pb1       = (const float*)d_in[8];
    const float* pW2       = (const float*)d_in[9];
    const float* pb2       = (const float*)d_in[10];
    float* out             = (float*)d_out;

    float *xcur, *acc, *t0, *t1, *wpk;
    cudaGetSymbolAddress((void**)&xcur, g_xcur);
    cudaGetSymbolAddress((void**)&acc,  g_acc);
    cudaGetSymbolAddress((void**)&t0,   g_t0);
    cudaGetSymbolAddress((void**)&t1,   g_t1);
    cudaGetSymbolAddress((void**)&wpk,  g_wpk);

    static int smem_set = 0;
    if (!smem_set) {
        cudaFuncSetAttribute(gemm_mma, cudaFuncAttributeMaxDynamicSharedMemorySize, GEMM_SMEM);
        smem_set = 1;
    }

    const int M = N_NODES;
    const int n4 = N_NODES * HDIM / 4;
    dim3 ggrid((M + BM - 1) / BM, HDIM / BN);   // 391 x 2
    const size_t WPK = (size_t)8 * 256 * 64;    // floats per weight

    detect_kernel<<<1, 32>>>((const unsigned*)edge_idx);
    convert_idx_kernel<<<(N_EDGES + 255) / 256, 256>>>(edge_idx);
    prep_weights<<<dim3(256, NWEIGHTS), 256>>>(Wm, pW1, pW2);
    copy_kernel<<<(n4 + 255) / 256, 256>>>((const float4*)x, (float4*)xcur, n4);

    for (int l = 0; l < N_LAYERS; l++) {
        const float* Wel = We + (size_t)l * 3 * HDIM;
        const float* bel = be + (size_t)l * HDIM;
        const float* bml = bmv + (size_t)l * 3 * HDIM;
        const int w0 = l * 3;

        copy_kernel<<<(n4 + 255) / 256, 256>>>((const float4*)xcur, (float4*)acc, n4);
        edge_kernel<<<4096, 256>>>(xcur, acc, edge_attr, Wel, bel);

        gemm_mma<<<ggrid, 256, GEMM_SMEM>>>(acc, wpk + (w0+0)*WPK, bml,          t0,   nullptr, M, 1);
        gemm_mma<<<ggrid, 256, GEMM_SMEM>>>(t0,  wpk + (w0+1)*WPK, bml + HDIM,   t1,   nullptr, M, 1);
        gemm_mma<<<ggrid, 256, GEMM_SMEM>>>(t1,  wpk + (w0+2)*WPK, bml + 2*HDIM, xcur, xcur,    M, 2);
    }
    gemm_mma<<<ggrid, 256, GEMM_SMEM>>>(xcur, wpk + 9*WPK,  pb1, t0,  nullptr, M, 1);
    gemm_mma<<<ggrid, 256, GEMM_SMEM>>>(t0,   wpk + 10*WPK, pb2, out, nullptr, M, 0);
}

// round 5
// speedup vs baseline: 1.6085x; 1.2172x over previous
#include <cuda_runtime.h>
#include <cuda_bf16.h>
#include <cstdint>

#define N_NODES 50000
#define N_EDGES 800000
#define HDIM    256
#define N_LAYERS 3
#define NWEIGHTS 11
#define MT 3125                 // 16-row tiles in M (50000/16 exactly)

// ---------------- scratch (no allocation allowed) ----------------
__device__ float g_xcur[N_NODES * HDIM];
__device__ float g_acc [N_NODES * HDIM];
// fragment-packed split activations: [buf][mt][k16][hi/lo][lane] uint4
__device__ uint4 g_apk[2][(size_t)MT * 16 * 2 * 32];
// fragment-packed split weights: [w][ch][n8][k2][hi/lo][lane] uint2
__device__ uint2 g_bpk[(size_t)NWEIGHTS * 8 * 32 * 2 * 2 * 32];
__device__ int   g_src [N_EDGES];
__device__ int   g_dst [N_EDGES];
__device__ int   g_is64;

// ---------------- helpers ----------------
__device__ __forceinline__ uint32_t smem_u32(const void* p) {
    uint32_t a;
    asm("{ .reg .u64 t; cvta.to.shared.u64 t, %1; cvt.u32.u64 %0, t; }" : "=r"(a) : "l"(p));
    return a;
}
__device__ __forceinline__ void cpa16(uint32_t dst, const void* src) {
    asm volatile("cp.async.cg.shared.global [%0], [%1], 16;" :: "r"(dst), "l"(src) : "memory");
}
// pack two floats to bf16x2 (e0 in low half)
__device__ __forceinline__ uint32_t pk2(float e0, float e1) {
    uint32_t r;
    asm("cvt.rn.bf16x2.f32 %0, %1, %2;" : "=r"(r) : "f"(e1), "f"(e0));
    return r;
}
__device__ __forceinline__ float lo16f(uint32_t r) { return __uint_as_float(r << 16); }
__device__ __forceinline__ float hi16f(uint32_t r) { return __uint_as_float(r & 0xFFFF0000u); }
__device__ __forceinline__ void split2(float v0, float v1, uint32_t& h, uint32_t& l) {
    h = pk2(v0, v1);
    l = pk2(v0 - lo16f(h), v1 - hi16f(h));
}
__device__ __forceinline__ void mma16(float* c, const uint4& a, uint32_t b0, uint32_t b1) {
    asm volatile("mma.sync.aligned.m16n8k16.row.col.f32.bf16.bf16.f32 "
                 "{%0,%1,%2,%3},{%4,%5,%6,%7},{%8,%9},{%0,%1,%2,%3};"
                 : "+f"(c[0]), "+f"(c[1]), "+f"(c[2]), "+f"(c[3])
                 : "r"(a.x), "r"(a.y), "r"(a.z), "r"(a.w), "r"(b0), "r"(b1));
}

// ---------------- misc kernels ----------------
__global__ void detect_kernel(const unsigned* __restrict__ ei) {
    if (threadIdx.x == 0 && blockIdx.x == 0) {
        int all0 = 1;
        #pragma unroll 1
        for (int i = 1; i < 128; i += 2) if (ei[i] != 0u) { all0 = 0; break; }
        g_is64 = all0;
    }
}
__global__ void convert_idx_kernel(const void* __restrict__ ei) {
    int i = blockIdx.x * blockDim.x + threadIdx.x;
    if (i >= N_EDGES) return;
    if (g_is64) {
        const long long* p = (const long long*)ei;
        g_src[i] = (int)p[i];
        g_dst[i] = (int)p[N_EDGES + i];
    } else {
        const int* p = (const int*)ei;
        g_src[i] = p[i];
        g_dst[i] = p[N_EDGES + i];
    }
}
__global__ void copy_kernel(const float4* __restrict__ src, float4* __restrict__ dst, int n4) {
    int i = blockIdx.x * blockDim.x + threadIdx.x;
    if (i < n4) dst[i] = src[i];
}

// split fp32 activations -> fragment-packed bf16 hi/lo  (block = 1 m-tile, 512 thr)
__global__ __launch_bounds__(512) void split_kernel(const float* __restrict__ src, uint4* __restrict__ dst) {
    int mt = blockIdx.x;
    int k16 = threadIdx.x >> 5, lane = threadIdx.x & 31;
    int g = lane >> 2, t = lane & 3;
    const float* r0 = src + (size_t)(mt * 16 + g) * HDIM + k16 * 16 + t * 2;
    const float* r1 = r0 + 8 * HDIM;
    float2 v00 = *(const float2*)r0, v01 = *(const float2*)(r0 + 8);
    float2 v10 = *(const float2*)r1, v11 = *(const float2*)(r1 + 8);
    uint4 h, l;
    split2(v00.x, v00.y, h.x, l.x);
    split2(v10.x, v10.y, h.y, l.y);
    split2(v01.x, v01.y, h.z, l.z);
    split2(v11.x, v11.y, h.w, l.w);
    size_t o = ((size_t)(mt * 16 + k16) * 2) * 32 + lane;
    dst[o] = h;
    dst[o + 32] = l;
}

// pre-split + fragment-pack all 11 weight matrices (source W[k][n] row-major)
__global__ void prep_w(const float* __restrict__ Wm, const float* __restrict__ pW1,
                       const float* __restrict__ pW2) {
    int w = blockIdx.z, n8 = blockIdx.y, k16 = blockIdx.x;
    int lane = threadIdx.x;
    const float* src = (w < 9) ? (Wm + (size_t)w * HDIM * HDIM) : ((w == 9) ? pW1 : pW2);
    int g = lane >> 2, t = lane & 3;
    int n = n8 * 8 + g;
    int kb = k16 * 16 + t * 2;
    float v0 = src[(size_t)kb * HDIM + n],       v1 = src[(size_t)(kb + 1) * HDIM + n];
    float w0 = src[(size_t)(kb + 8) * HDIM + n], w1 = src[(size_t)(kb + 9) * HDIM + n];
    uint2 hh, ll;
    split2(v0, v1, hh.x, ll.x);
    split2(w0, w1, hh.y, ll.y);
    int ch = k16 >> 1, k2 = k16 & 1;
    size_t o = ((((size_t)w * 8 + ch) * 32 + n8) * 2 + k2) * 2 * 32 + lane;
    g_bpk[o] = hh;
    g_bpk[o + 32] = ll;
}

// ---------------- edge phase ----------------
__device__ __forceinline__ void red_add_v4(float* p, float4 v) {
    asm volatile("red.global.add.v4.f32 [%0], {%1,%2,%3,%4};"
                 :: "l"(p), "f"(v.x), "f"(v.y), "f"(v.z), "f"(v.w) : "memory");
}
__global__ __launch_bounds__(256) void edge_kernel(
    const float* __restrict__ x, float* __restrict__ acc,
    const float* __restrict__ edge_attr, const float* __restrict__ We, const float* __restrict__ be)
{
    __shared__ float sW[3 * HDIM];
    __shared__ float sB[HDIM];
    int tid = threadIdx.x;
    for (int i = tid; i < 3 * HDIM; i += 256) sW[i] = We[i];
    if (tid < HDIM) sB[tid] = be[tid];
    __syncthreads();
    int warp = tid >> 5, lane = tid & 31;
    int nwarps = gridDim.x * 8;
    for (int e = blockIdx.x * 8 + warp; e < N_EDGES; e += nwarps) {
        int s = g_src[e], d = g_dst[e];
        float a0 = __ldg(&edge_attr[e * 3 + 0]);
        float a1 = __ldg(&edge_attr[e * 3 + 1]);
        float a2 = __ldg(&edge_attr[e * 3 + 2]);
        const float4* xs = (const float4*)(x + (size_t)s * HDIM);
        float* ad = acc + (size_t)d * HDIM;
        #pragma unroll
        for (int j = 0; j < 2; j++) {
            int h = lane * 8 + j * 4;
            float4 xv = __ldg(&xs[h >> 2]);
            float4 m;
            m.x = fmaxf(xv.x + fmaf(a0, sW[h+0], fmaf(a1, sW[HDIM+h+0], fmaf(a2, sW[2*HDIM+h+0], sB[h+0]))), 0.f);
            m.y = fmaxf(xv.y + fmaf(a0, sW[h+1], fmaf(a1, sW[HDIM+h+1], fmaf(a2, sW[2*HDIM+h+1], sB[h+1]))), 0.f);
            m.z = fmaxf(xv.z + fmaf(a0, sW[h+2], fmaf(a1, sW[HDIM+h+2], fmaf(a2, sW[2*HDIM+h+2], sB[h+2]))), 0.f);
            m.w = fmaxf(xv.w + fmaf(a0, sW[h+3], fmaf(a1, sW[HDIM+h+3], fmaf(a2, sW[2*HDIM+h+3], sB[h+3]))), 0.f);
            red_add_v4(ad + h, m);
        }
    }
}

// ---------------- bf16-split mma GEMM v3 ----------------
// A pre-split fragment-packed (g_apk layout); B pre-split fragment-packed (g_bpk).
// Outputs: optional fp32 C, optional next-gemm packed A (hi/lo).
// mode: 0 = none, 1 = relu, 2 = relu + residual(res)
__global__ __launch_bounds__(256, 2) void gemm_bf(
    const uint4* __restrict__ Apk, const uint2* __restrict__ Bpk,
    const float* __restrict__ bias, float* __restrict__ Cf, uint4* __restrict__ Opk,
    const float* __restrict__ res, int mode)
{
    __shared__ uint2 sb[2][2048];           // 2 x 16KB B staging
    const uint32_t sbase = smem_u32(sb);
    const int tid  = threadIdx.x;
    const int lane = tid & 31;
    const int warp = tid >> 5;
    const int g = lane >> 2, t = lane & 3;
    const int wm = warp & 3;                // 4 warps along M (32 rows each)
    const int wn = warp >> 2;               // 2 warps along N (64 cols each)
    const int bm = blockIdx.x * 128;
    const int bn = blockIdx.y * 128;
    const int bn8 = bn >> 3;

    float acc[2][8][4];
    #pragma unroll
    for (int i = 0; i < 2; i++)
        #pragma unroll
        for (int j = 0; j < 8; j++)
            #pragma unroll
            for (int q = 0; q < 4; q++) acc[i][j][q] = 0.f;

    const int mt0 = bm >> 4;
    const int mtA = mt0 + wm * 2;
    const bool ok0 = (mtA + 0) < MT;
    const bool ok1 = (mtA + 1) < MT;

    auto issue = [&](int ch, int buf) {
        const uint4* src = (const uint4*)(Bpk + ((size_t)ch * 32 + bn8) * 128);
        uint32_t dst = sbase + buf * 16384 + tid * 16;
        #pragma unroll
        for (int i = 0; i < 4; i++) cpa16(dst + i * 4096, src + tid + i * 256);
        asm volatile("cp.async.commit_group;" ::: "memory");
    };
    auto ldA = [&](int k16, uint4 fr[2][2]) {
        #pragma unroll
        for (int mi = 0; mi < 2; mi++) {
            bool ok = mi ? ok1 : ok0;
            size_t o = ((size_t)((mtA + mi) * 16 + k16) * 2) * 32 + lane;
            if (ok) {
                fr[mi][0] = __ldg(Apk + o);
                fr[mi][1] = __ldg(Apk + o + 32);
            } else {
                fr[mi][0] = make_uint4(0, 0, 0, 0);
                fr[mi][1] = make_uint4(0, 0, 0, 0);
            }
        }
    };

    issue(0, 0);
    issue(1, 1);

    uint4 af[2][2], an[2][2];
    ldA(0, af);

    #pragma unroll 1
    for (int ch = 0; ch < 8; ch++) {
        const int buf = ch & 1;
        if (ch == 7) asm volatile("cp.async.wait_group 0;" ::: "memory");
        else         asm volatile("cp.async.wait_group 1;" ::: "memory");
        __syncthreads();

        #pragma unroll
        for (int k2 = 0; k2 < 2; k2++) {
            const int k16 = ch * 2 + k2;
            if (k16 < 15) ldA(k16 + 1, an);
            const uint2* bs = sb[buf];
            // hi-B pass: ah*bh and al*bh
            uint2 bh[8];
            #pragma unroll
            for (int ni = 0; ni < 8; ni++)
                bh[ni] = bs[(wn * 8 + ni) * 128 + k2 * 64 + lane];
            #pragma unroll
            for (int mi = 0; mi < 2; mi++)
                #pragma unroll
                for (int ni = 0; ni < 8; ni++) {
                    mma16(acc[mi][ni], af[mi][0], bh[ni].x, bh[ni].y);
                    mma16(acc[mi][ni], af[mi][1], bh[ni].x, bh[ni].y);
                }
            // lo-B pass: ah*bl
            uint2 bl[8];
            #pragma unroll
            for (int ni = 0; ni < 8; ni++)
                bl[ni] = bs[(wn * 8 + ni) * 128 + k2 * 64 + 32 + lane];
            #pragma unroll
            for (int mi = 0; mi < 2; mi++)
                #pragma unroll
                for (int ni = 0; ni < 8; ni++)
                    mma16(acc[mi][ni], af[mi][0], bl[ni].x, bl[ni].y);
            if (k16 < 15) {
                #pragma unroll
                for (int mi = 0; mi < 2; mi++) {
                    af[mi][0] = an[mi][0];
                    af[mi][1] = an[mi][1];
                }
            }
        }
        __syncthreads();
        if (ch + 2 < 8) issue(ch + 2, buf);
    }

    // ---- epilogue: bias / relu / residual in-place on acc ----
    #pragma unroll
    for (int ni = 0; ni < 8; ni++) {
        int col = bn + wn * 64 + ni * 8 + t * 2;
        float2 bb = *(const float2*)(bias + col);
        #pragma unroll
        for (int mi = 0; mi < 2; mi++) {
            float* c = acc[mi][ni];
            c[0] += bb.x; c[1] += bb.y; c[2] += bb.x; c[3] += bb.y;
            if (mode >= 1) {
                c[0] = fmaxf(c[0], 0.f); c[1] = fmaxf(c[1], 0.f);
                c[2] = fmaxf(c[2], 0.f); c[3] = fmaxf(c[3], 0.f);
            }
            if (mode == 2) {
                bool ok = mi ? ok1 : ok0;
                if (ok) {
                    int row0 = bm + wm * 32 + mi * 16 + g;
                    float2 r0 = *(const float2*)(res + (size_t)row0 * HDIM + col);
                    float2 r1 = *(const float2*)(res + (size_t)(row0 + 8) * HDIM + col);
                    c[0] += r0.x; c[1] += r0.y; c[2] += r1.x; c[3] += r1.y;
                }
            }
        }
    }
    // fp32 store
    if (Cf) {
        #pragma unroll
        for (int mi = 0; mi < 2; mi++) {
            bool ok = mi ? ok1 : ok0;
            if (!ok) continue;
            int row0 = bm + wm * 32 + mi * 16 + g;
            #pragma unroll
            for (int ni = 0; ni < 8; ni++) {
                int col = bn + wn * 64 + ni * 8 + t * 2;
                float* c = acc[mi][ni];
                *(float2*)(Cf + (size_t)row0 * HDIM + col)       = make_float2(c[0], c[1]);
                *(float2*)(Cf + (size_t)(row0 + 8) * HDIM + col) = make_float2(c[2], c[3]);
            }
        }
    }
    // packed split store (accumulator fragments == next GEMM's A fragments)
    if (Opk) {
        #pragma unroll
        for (int mi = 0; mi < 2; mi++) {
            bool ok = mi ? ok1 : ok0;
            if (!ok) continue;
            int mt = mtA + mi;
            #pragma unroll
            for (int nip = 0; nip < 4; nip++) {
                float* c0 = acc[mi][nip * 2];
                float* c1 = acc[mi][nip * 2 + 1];
                uint4 h, l;
                split2(c0[0], c0[1], h.x, l.x);
                split2(c0[2], c0[3], h.y, l.y);
                split2(c1[0], c1[1], h.z, l.z);
                split2(c1[2], c1[3], h.w, l.w);
                int k16o = (bn + wn * 64 + nip * 16) >> 4;
                size_t o = ((size_t)(mt * 16 + k16o) * 2) * 32 + lane;
                Opk[o] = h;
                Opk[o + 32] = l;
            }
        }
    }
}

// ---------------- launch ----------------
extern "C" void kernel_launch(void* const* d_in, const int* in_sizes, int n_in,
                              void* d_out, int out_size)
{
    const float* x         = (const float*)d_in[0];
    const void*  edge_idx  = d_in[1];
    const float* edge_attr = (const float*)d_in[2];
    const float* We        = (const float*)d_in[3];
    const float* be        = (const float*)d_in[4];
    const float* Wm        = (const float*)d_in[5];
    const float* bmv       = (const float*)d_in[6];
    const float* pW1       = (const float*)d_in[7];
    const float* pb1       = (const float*)d_in[8];
    const float* pW2       = (const float*)d_in[9];
    const float* pb2       = (const float*)d_in[10];
    float* out             = (float*)d_out;

    float *xcur, *acc;
    uint4 *apk;
    uint2 *bpk;
    cudaGetSymbolAddress((void**)&xcur, g_xcur);
    cudaGetSymbolAddress((void**)&acc,  g_acc);
    cudaGetSymbolAddress((void**)&apk,  g_apk);
    cudaGetSymbolAddress((void**)&bpk,  g_bpk);
    uint4* apk0 = apk;
    uint4* apk1 = apk + (size_t)MT * 16 * 2 * 32;

    const int n4 = N_NODES * HDIM / 4;
    dim3 ggrid((N_NODES + 127) / 128, 2);          // 391 x 2
    const size_t BW = (size_t)8 * 32 * 2 * 2 * 32; // uint2 per weight

    detect_kernel<<<1, 32>>>((const unsigned*)edge_idx);
    convert_idx_kernel<<<(N_EDGES + 255) / 256, 256>>>(edge_idx);
    prep_w<<<dim3(16, 32, NWEIGHTS), 32>>>(Wm, pW1, pW2);
    copy_kernel<<<(n4 + 255) / 256, 256>>>((const float4*)x, (float4*)xcur, n4);

    for (int l = 0; l < N_LAYERS; l++) {
        const float* Wel = We + (size_t)l * 3 * HDIM;
        const float* bel = be + (size_t)l * HDIM;
        const float* bml = bmv + (size_t)l * 3 * HDIM;
        const int w0 = l * 3;

        copy_kernel<<<(n4 + 255) / 256, 256>>>((const float4*)xcur, (float4*)acc, n4);
        edge_kernel<<<4096, 256>>>(xcur, acc, edge_attr, Wel, bel);
        split_kernel<<<MT, 512>>>(acc, apk0);

        gemm_bf<<<ggrid, 256>>>(apk0, bpk + (w0+0)*BW, bml,          nullptr, apk1, nullptr, 1);
        gemm_bf<<<ggrid, 256>>>(apk1, bpk + (w0+1)*BW, bml + HDIM,   nullptr, apk0, nullptr, 1);
        gemm_bf<<<ggrid, 256>>>(apk0, bpk + (w0+2)*BW, bml + 2*HDIM, xcur,    apk1, xcur,    2);
    }
    gemm_bf<<<ggrid, 256>>>(apk1, bpk + 9*BW,  pb1, nullptr, apk0, nullptr, 1);
    gemm_bf<<<ggrid, 256>>>(apk0, bpk + 10*BW, pb2, out,     nullptr, nullptr, 0);
}